// round 1
// baseline (speedup 1.0000x reference)
#include <cuda_runtime.h>
#include <math.h>

#define BB 8
#define TT 64
#define NN 256
#define HH 256
#define DI 6
#define DO 9
#define G3 (3*HH)   // 768

// ---------------- scratch (device globals; no runtime allocation) ----------------
__device__ __align__(16) float g_gx[(size_t)BB*TT*NN*G3];     // 402 MB: gx for current layer, all t
__device__ __align__(16) float g_hseq[(size_t)BB*TT*NN*HH];   // 134 MB: hidden sequence of current layer
__device__ __align__(16) float g_Axseq[(size_t)BB*TT*NN*HH];  // 134 MB: A ⊛ hseq (layer-1 prep)
__device__ __align__(16) float g_h [BB*NN*HH];
__device__ __align__(16) float g_Ah[BB*NN*HH];
__device__ __align__(16) float g_z [BB*NN*HH];
__device__ __align__(16) float g_u [BB*NN*HH];
__device__ __align__(16) float g_Au[BB*NN*HH];
__device__ int   g_cnt[NN];
__device__ int   g_col[NN*NN];
__device__ float g_val[NN*NN];

__device__ __forceinline__ float sigmoidf_(float x){ return 1.0f / (1.0f + expf(-x)); }

// ---------------- CSR build from dense adjacency (zeros are exact) ----------------
__global__ void build_csr(const float* __restrict__ adj){
    int n = threadIdx.x;
    int c = 0;
    for (int m = 0; m < NN; m++){
        float v = adj[n*NN + m];
        if (v != 0.0f){ g_col[n*NN + c] = m; g_val[n*NN + c] = v; c++; }
    }
    g_cnt[n] = c;
}

__global__ void zero_h(){
    int i = blockIdx.x * 256 + threadIdx.x;
    g_h[i] = 0.0f;
}

// ---------------- layer-0 gx: per (b,t), gx = (A ⊛ (x*mask)) @ Wx0 + b0 ----------------
__global__ void prep_gx0(const float* __restrict__ x2d, const float* __restrict__ mask,
                         const float* __restrict__ Wx0, const float* __restrict__ b0){
    __shared__ float xm[NN*DI];
    __shared__ float ax[NN*DI];
    __shared__ float Ws[DI*G3];
    int bt = blockIdx.x;
    int tid = threadIdx.x;

    for (int i = tid; i < NN*DI; i += 256){
        int n = i / DI;
        xm[i] = x2d[(size_t)bt*NN*DI + i] * mask[(size_t)bt*NN + n];
    }
    for (int i = tid; i < DI*G3; i += 256) Ws[i] = Wx0[i];
    __syncthreads();

    {   // sparse conv: one node per thread
        int n = tid;
        float a0=0,a1=0,a2=0,a3=0,a4=0,a5=0;
        int cn = g_cnt[n];
        for (int e = 0; e < cn; e++){
            int m = g_col[n*NN + e];
            float w = g_val[n*NN + e];
            const float* xr = xm + m*DI;
            a0 += w*xr[0]; a1 += w*xr[1]; a2 += w*xr[2];
            a3 += w*xr[3]; a4 += w*xr[4]; a5 += w*xr[5];
        }
        float* ar = ax + n*DI;
        ar[0]=a0; ar[1]=a1; ar[2]=a2; ar[3]=a3; ar[4]=a4; ar[5]=a5;
    }
    __syncthreads();

    for (int jj = 0; jj < 3; jj++){
        int j = tid + (jj << 8);
        float w0=Ws[j], w1=Ws[G3+j], w2=Ws[2*G3+j], w3=Ws[3*G3+j], w4=Ws[4*G3+j], w5=Ws[5*G3+j];
        float bj = b0[j];
        float* gout = g_gx + (size_t)bt*NN*G3 + j;
        for (int n = 0; n < NN; n++){
            const float* axr = ax + n*DI;
            float s = bj + axr[0]*w0 + axr[1]*w1 + axr[2]*w2
                         + axr[3]*w3 + axr[4]*w4 + axr[5]*w5;
            gout[(size_t)n*G3] = s;
        }
    }
}

// ---------------- per-step sparse conv: C[q,n,:] = sum_e w * X[q,col,:] ----------------
__global__ void spconv_step(int which){
    const float* __restrict__ X = which ? g_u  : g_h;
    float* __restrict__       C = which ? g_Au : g_Ah;
    int n = blockIdx.x & 255;
    int q = blockIdx.x >> 8;
    int k = threadIdx.x;
    int cn = g_cnt[n];
    const int*   cp = g_col + n*NN;
    const float* vp = g_val + n*NN;
    const float* Xb = X + (size_t)q*NN*HH + k;
    float a0 = 0.0f, a1 = 0.0f;
    int e = 0;
    for (; e + 2 <= cn; e += 2){
        a0 += vp[e]   * Xb[cp[e]   << 8];
        a1 += vp[e+1] * Xb[cp[e+1] << 8];
    }
    if (e < cn) a0 += vp[e] * Xb[cp[e] << 8];
    C[(size_t)q*NN*HH + (n << 8) + k] = a0 + a1;
}

// ---------------- sequence sparse conv (layer-1 prep): g_Axseq = A ⊛ g_hseq ----------------
// block = (k-slice of 32, q = b*T+t); stages X[q][:, slice] in smem (32 KB)
__global__ void spconv_seq(){
    __shared__ float Xs[NN*32];
    int kh = blockIdx.x;       // 0..7
    int q  = blockIdx.y;       // 0..511
    int tid = threadIdx.x;
    const float4* X4 = (const float4*)g_hseq;
    float4* Xs4 = (float4*)Xs;
    for (int i = tid; i < NN*8; i += 256){
        int m = i >> 3, c4 = i & 7;
        Xs4[i] = X4[((size_t)q*NN + m)*64 + kh*8 + c4];
    }
    __syncthreads();
    int k  = tid & 31;
    int ng = tid >> 5;         // 0..7
    for (int nb = 0; nb < NN; nb += 8){
        int n = nb + ng;
        int cn = g_cnt[n];
        const int*   cp = g_col + n*NN;
        const float* vp = g_val + n*NN;
        float a0 = 0.0f, a1 = 0.0f;
        int e = 0;
        for (; e + 2 <= cn; e += 2){
            a0 += vp[e]   * Xs[(cp[e]   << 5) + k];
            a1 += vp[e+1] * Xs[(cp[e+1] << 5) + k];
        }
        if (e < cn) a0 += vp[e] * Xs[(cp[e] << 5) + k];
        g_Axseq[((size_t)q*NN + n)*HH + (kh << 5) + k] = a0 + a1;
    }
}

// ---------------- shared 64x64x16 fp32 GEMM body ----------------
#define GEMM64x64(ABASE, ALd, BBASE, BLd)                                           \
    do {                                                                            \
        for (int kk = 0; kk < HH; kk += 16){                                        \
            float4 av = *(const float4*)((ABASE) + (size_t)(r0+li)*(ALd) + kk + lp4); \
            As[lp4+0][li]=av.x; As[lp4+1][li]=av.y; As[lp4+2][li]=av.z; As[lp4+3][li]=av.w; \
            float4 bv = *(const float4*)((BBASE) + (size_t)(kk+bp)*(BLd) + bj4);    \
            *(float4*)&Bs[bp][bj4] = bv;                                            \
            __syncthreads();                                                        \
            _Pragma("unroll")                                                       \
            for (int p = 0; p < 16; p++){                                           \
                float4 a = *(const float4*)&As[p][ty*4];                            \
                float4 b = *(const float4*)&Bs[p][tx*4];                            \
                acc[0][0]+=a.x*b.x; acc[0][1]+=a.x*b.y; acc[0][2]+=a.x*b.z; acc[0][3]+=a.x*b.w; \
                acc[1][0]+=a.y*b.x; acc[1][1]+=a.y*b.y; acc[1][2]+=a.y*b.z; acc[1][3]+=a.y*b.w; \
                acc[2][0]+=a.z*b.x; acc[2][1]+=a.z*b.y; acc[2][2]+=a.z*b.z; acc[2][3]+=a.z*b.w; \
                acc[3][0]+=a.w*b.x; acc[3][1]+=a.w*b.y; acc[3][2]+=a.w*b.z; acc[3][3]+=a.w*b.w; \
            }                                                                       \
            __syncthreads();                                                        \
        }                                                                           \
    } while(0)

#define GEMM_PROLOGUE                          \
    __shared__ float As[16][64];               \
    __shared__ float Bs[16][64];               \
    int tid = threadIdx.x;                     \
    int r0 = blockIdx.y * 64;                  \
    int j0 = blockIdx.x * 64;                  \
    int ty = tid >> 4, tx = tid & 15;          \
    int li = tid >> 2;                         \
    int lp4 = (tid & 3) * 4;                   \
    int bp = tid >> 4;                         \
    int bj4 = (tid & 15) * 4;                  \
    float acc[4][4] = {};

// z/r gates: gzr = Ah @ Wh[:, :512] + gx[:, :512]; z=sig, r=sig, u=r*h
__global__ void gemm_zr(const float* __restrict__ Wh, int t){
    GEMM_PROLOGUE
    GEMM64x64(g_Ah, HH, Wh + j0, G3);
    #pragma unroll
    for (int ii = 0; ii < 4; ii++)
    #pragma unroll
    for (int jj = 0; jj < 4; jj++){
        int r = r0 + ty*4 + ii;
        int j = j0 + tx*4 + jj;
        int b = r >> 8, n = r & 255;
        float val = acc[ii][jj] + g_gx[(((size_t)(b*TT + t))*NN + n)*G3 + j];
        if (j < HH){
            g_z[(size_t)r*HH + j] = sigmoidf_(val);
        } else {
            int j2 = j - HH;
            float rr = sigmoidf_(val);
            g_u[(size_t)r*HH + j2] = rr * g_h[(size_t)r*HH + j2];
        }
    }
}

// c gate + state update: c = tanh(Au @ Wh[:,512:] + gx[:,512:]); h = z*h + (1-z)*c
__global__ void gemm_c(const float* __restrict__ Wh, int t){
    GEMM_PROLOGUE
    GEMM64x64(g_Au, HH, Wh + 512 + j0, G3);
    #pragma unroll
    for (int ii = 0; ii < 4; ii++)
    #pragma unroll
    for (int jj = 0; jj < 4; jj++){
        int r = r0 + ty*4 + ii;
        int j = j0 + tx*4 + jj;
        int b = r >> 8, n = r & 255;
        float val = acc[ii][jj] + g_gx[(((size_t)(b*TT + t))*NN + n)*G3 + 512 + j];
        float c = tanhf(val);
        size_t idx = (size_t)r*HH + j;
        float zv = g_z[idx];
        float hn = zv * g_h[idx] + (1.0f - zv) * c;
        g_h[idx] = hn;
        g_hseq[(((size_t)(b*TT + t))*NN + n)*HH + j] = hn;
    }
}

// layer-1 gx: g_gx = g_Axseq @ Wx1 + b1   ([131072,256] x [256,768])
__global__ void gemm_gx1(const float* __restrict__ Wx1, const float* __restrict__ b1){
    GEMM_PROLOGUE
    GEMM64x64(g_Axseq, HH, Wx1 + j0, G3);
    #pragma unroll
    for (int ii = 0; ii < 4; ii++)
    #pragma unroll
    for (int jj = 0; jj < 4; jj++){
        int r = r0 + ty*4 + ii;
        int j = j0 + tx*4 + jj;
        g_gx[(size_t)r*G3 + j] = acc[ii][jj] + b1[j];
    }
}

// output head: out = g_hseq @ Wout + bout   ([131072,256] x [256,9])
__global__ void out_head(const float* __restrict__ Wout, const float* __restrict__ bout,
                         float* __restrict__ out){
    __shared__ float sh[32*257];
    __shared__ float Ws[HH*DO];
    __shared__ float bs[DO];
    int r0 = blockIdx.x * 32;
    int tid = threadIdx.x;
    for (int i = tid; i < HH*DO; i += 256) Ws[i] = Wout[i];
    if (tid < DO) bs[tid] = bout[tid];
    const float4* H4 = (const float4*)g_hseq;
    for (int i = tid; i < 32*64; i += 256){
        int rr = i >> 6, c4 = i & 63;
        float4 v = H4[((size_t)(r0 + rr))*64 + c4];
        float* dst = &sh[rr*257 + c4*4];
        dst[0]=v.x; dst[1]=v.y; dst[2]=v.z; dst[3]=v.w;
    }
    __syncthreads();
    for (int oi = tid; oi < 32*DO; oi += 256){
        int rr = oi / DO, c = oi % DO;
        float a0 = bs[c], a1 = 0.0f;
        const float* sr = &sh[rr*257];
        for (int k = 0; k < HH; k += 2){
            a0 += sr[k]   * Ws[k*DO + c];
            a1 += sr[k+1] * Ws[(k+1)*DO + c];
        }
        out[(size_t)(r0 + rr)*DO + c] = a0 + a1;
    }
}

// ---------------- launch ----------------
extern "C" void kernel_launch(void* const* d_in, const int* in_sizes, int n_in,
                              void* d_out, int out_size) {
    const float* x2d  = (const float*)d_in[0];
    const float* mask = (const float*)d_in[1];
    const float* adj  = (const float*)d_in[2];
    const float* Wx0  = (const float*)d_in[3];
    const float* Wh0  = (const float*)d_in[4];
    const float* b0   = (const float*)d_in[5];
    const float* Wx1  = (const float*)d_in[6];
    const float* Wh1  = (const float*)d_in[7];
    const float* b1   = (const float*)d_in[8];
    const float* Wout = (const float*)d_in[9];
    const float* bout = (const float*)d_in[10];
    float* out = (float*)d_out;

    build_csr<<<1, 256>>>(adj);
    prep_gx0<<<BB*TT, 256>>>(x2d, mask, Wx0, b0);

    // ---- layer 0 recurrence ----
    zero_h<<<2048, 256>>>();
    for (int t = 0; t < TT; t++){
        spconv_step<<<BB*NN, 256>>>(0);
        gemm_zr<<<dim3(8, (BB*NN)/64), 256>>>(Wh0, t);
        spconv_step<<<BB*NN, 256>>>(1);
        gemm_c<<<dim3(4, (BB*NN)/64), 256>>>(Wh0, t);
    }

    // ---- layer 1 gx precompute (parallel over all t) ----
    spconv_seq<<<dim3(8, BB*TT), 256>>>();
    gemm_gx1<<<dim3(12, (BB*TT*NN)/64), 256>>>(Wx1, b1);

    // ---- layer 1 recurrence ----
    zero_h<<<2048, 256>>>();
    for (int t = 0; t < TT; t++){
        spconv_step<<<BB*NN, 256>>>(0);
        gemm_zr<<<dim3(8, (BB*NN)/64), 256>>>(Wh1, t);
        spconv_step<<<BB*NN, 256>>>(1);
        gemm_c<<<dim3(4, (BB*NN)/64), 256>>>(Wh1, t);
    }

    // ---- output head ----
    out_head<<<(BB*TT*NN)/32, 256>>>(Wout, bout, out);
}